// round 7
// baseline (speedup 1.0000x reference)
#include <cuda_runtime.h>
#include <cuda_bf16.h>
#include <math.h>
#include <stdint.h>

// ---------------- problem constants ----------------
#define BB   2
#define TT   2048
#define DD   1024
#define NHH  16
#define HDD  64
#define FFD  4096
#define NLL  2
#define VV   32000
#define MM   (BB*TT)          // 4096 rows
#define EPSF 1.1920929e-07f

// ---------------- scratch (device globals; no allocation allowed) ------------
__device__ float g_h  [MM * DD];        // residual stream (fp32)
__device__ float g_qkv[MM * 3 * DD];    // qkv projections (fp32)
__device__ float g_fg [MM * FFD];       // gate (silu applied, fp32)
__device__ float g_fu [MM * FFD];       // up (fp32)
__device__ __nv_bfloat16 g_nh [MM * DD];    // rmsnorm out hi/lo planes
__device__ __nv_bfloat16 g_nl [MM * DD];
__device__ __nv_bfloat16 g_ah [MM * DD];    // attention out hi/lo
__device__ __nv_bfloat16 g_al [MM * DD];
__device__ __nv_bfloat16 g_fgh[MM * FFD];   // gate*up hi/lo
__device__ __nv_bfloat16 g_fgl[MM * FFD];
__device__ __nv_bfloat16 g_wh [VV * DD];    // split weights (max = head)
__device__ __nv_bfloat16 g_wl [VV * DD];

// ---------------- small helpers ----------------
__device__ __forceinline__ uint32_t s2u(const void* p) {
    uint32_t a;
    asm("{ .reg .u64 t; cvta.to.shared.u64 t, %1; cvt.u32.u64 %0, t; }" : "=r"(a) : "l"(p));
    return a;
}
__device__ __forceinline__ void bsplit(float x, __nv_bfloat16& hi, __nv_bfloat16& lo) {
    hi = __float2bfloat16(x);
    lo = __float2bfloat16(x - __bfloat162float(hi));
}
__device__ __forceinline__ void mma16(float* c, const uint32_t* a, const uint32_t* b) {
    asm volatile(
        "mma.sync.aligned.m16n8k16.row.col.f32.bf16.bf16.f32 "
        "{%0,%1,%2,%3}, {%4,%5,%6,%7}, {%8,%9}, {%0,%1,%2,%3};"
        : "+f"(c[0]), "+f"(c[1]), "+f"(c[2]), "+f"(c[3])
        : "r"(a[0]), "r"(a[1]), "r"(a[2]), "r"(a[3]), "r"(b[0]), "r"(b[1]));
}

// ---------------- embedding gather ----------------
__global__ void embed_kernel(const int* __restrict__ x,
                             const float* __restrict__ emb,
                             float* __restrict__ h)
{
    int row = blockIdx.x;
    int t   = threadIdx.x;                // 256 threads, float4 each
    int id  = x[row];
    const float4* src = (const float4*)(emb + (size_t)id * DD);
    float4*       dst = (float4*)(h + (size_t)row * DD);
    dst[t] = src[t];
}

// ---------------- RMSNorm -> hi/lo bf16 planes ----------------
__global__ void rmsnorm_kernel(const float* __restrict__ in,
                               const float* __restrict__ w,
                               __nv_bfloat16* __restrict__ oh,
                               __nv_bfloat16* __restrict__ ol)
{
    int row = blockIdx.x;
    int t   = threadIdx.x;
    const float4* r4 = (const float4*)(in + (size_t)row * DD);
    float4 v = r4[t];
    float ss = v.x*v.x + v.y*v.y + v.z*v.z + v.w*v.w;
    #pragma unroll
    for (int o = 16; o; o >>= 1) ss += __shfl_xor_sync(0xffffffffu, ss, o);
    __shared__ float red[8];
    if ((t & 31) == 0) red[t >> 5] = ss;
    __syncthreads();
    __shared__ float scale_sh;
    if (t == 0) {
        float s = 0.f;
        #pragma unroll
        for (int i = 0; i < 8; i++) s += red[i];
        scale_sh = rsqrtf(s / (float)DD + EPSF);
    }
    __syncthreads();
    float sc = scale_sh;
    const float4* w4 = (const float4*)w;
    float4 wv = w4[t];
    __nv_bfloat16 hx,lx, hy,ly, hz,lz, hw,lw;
    bsplit(v.x * sc * wv.x, hx, lx);
    bsplit(v.y * sc * wv.y, hy, ly);
    bsplit(v.z * sc * wv.z, hz, lz);
    bsplit(v.w * sc * wv.w, hw, lw);
    __nv_bfloat162* ph = (__nv_bfloat162*)(oh + (size_t)row * DD);
    __nv_bfloat162* pl = (__nv_bfloat162*)(ol + (size_t)row * DD);
    ph[2*t]   = __halves2bfloat162(hx, hy);
    ph[2*t+1] = __halves2bfloat162(hz, hw);
    pl[2*t]   = __halves2bfloat162(lx, ly);
    pl[2*t+1] = __halves2bfloat162(lz, lw);
}

// ---------------- weight split pass (fp32 -> hi/lo bf16 planes) --------------
__global__ void wsplit_kernel(const float* __restrict__ in,
                              __nv_bfloat16* __restrict__ oh,
                              __nv_bfloat16* __restrict__ ol, int n4)
{
    int i = blockIdx.x * blockDim.x + threadIdx.x;
    if (i < n4) {
        float4 v = ((const float4*)in)[i];
        __nv_bfloat16 hx,lx, hy,ly, hz,lz, hw,lw;
        bsplit(v.x, hx, lx); bsplit(v.y, hy, ly);
        bsplit(v.z, hz, lz); bsplit(v.w, hw, lw);
        ((__nv_bfloat162*)oh)[2*i]   = __halves2bfloat162(hx, hy);
        ((__nv_bfloat162*)oh)[2*i+1] = __halves2bfloat162(hz, hw);
        ((__nv_bfloat162*)ol)[2*i]   = __halves2bfloat162(lx, ly);
        ((__nv_bfloat162*)ol)[2*i+1] = __halves2bfloat162(lz, lw);
    }
}

// ---------------- gate*up -> hi/lo bf16 planes ----------------
__global__ void mul_kernel(const float* __restrict__ g, const float* __restrict__ u,
                           __nv_bfloat16* __restrict__ oh,
                           __nv_bfloat16* __restrict__ ol, int n4)
{
    int i = blockIdx.x * blockDim.x + threadIdx.x;
    if (i < n4) {
        float4 a = ((const float4*)g)[i];
        float4 b = ((const float4*)u)[i];
        __nv_bfloat16 hx,lx, hy,ly, hz,lz, hw,lw;
        bsplit(a.x * b.x, hx, lx); bsplit(a.y * b.y, hy, ly);
        bsplit(a.z * b.z, hz, lz); bsplit(a.w * b.w, hw, lw);
        ((__nv_bfloat162*)oh)[2*i]   = __halves2bfloat162(hx, hy);
        ((__nv_bfloat162*)oh)[2*i+1] = __halves2bfloat162(hz, hw);
        ((__nv_bfloat162*)ol)[2*i]   = __halves2bfloat162(lx, ly);
        ((__nv_bfloat162*)ol)[2*i+1] = __halves2bfloat162(lz, lw);
    }
}

// ============================================================================
// bf16x3 GEMM: C[M,N] = (Ahi+Alo)[M,K] * (Whi+Wlo)[N,K]^T (+bias)(+epi)
// 3 bf16 m16n8k16 MMAs per tile-step: hi*hi + hi*lo + lo*hi (~fp32 accurate).
// CTA tile 128x128, K-chunk 32, 3-stage cp.async pipeline, 8 warps (4x2),
// warp tile 32(M)x64(N). XOR-swizzled smem, stride 16 b32 (no padding).
// EPI: 0 = bias only, 1 = bias + residual, 2 = bias + silu
// ============================================================================
#define SWZ(r,j)   ((r)*16 + ((j) ^ (((((r)>>1))&3)<<2)))
#define STG_U32    8192                        // 4 planes * 128 rows * 16 b32
#define GEMM_SMEM  (3 * STG_U32 * 4)           // 98304 bytes

template<int EPI>
__global__ void __launch_bounds__(256, 2)
gemm_bf3(const __nv_bfloat16* __restrict__ Ahi, const __nv_bfloat16* __restrict__ Alo,
         const __nv_bfloat16* __restrict__ Whi, const __nv_bfloat16* __restrict__ Wlo,
         const float* __restrict__ bias, const float* __restrict__ res,
         float* __restrict__ C, int N, int K)
{
    extern __shared__ uint32_t smu[];
    const int tid  = threadIdx.x;
    const int wid  = tid >> 5;
    const int lane = tid & 31;
    const int g    = lane >> 2;     // 0..7
    const int t    = lane & 3;      // 0..3
    const int wm   = (wid >> 1) * 32;   // warp M offset
    const int wn   = (wid & 1) * 64;    // warp N offset

    const __nv_bfloat16* Agh = Ahi + (size_t)blockIdx.y * 128 * K;
    const __nv_bfloat16* Agl = Alo + (size_t)blockIdx.y * 128 * K;
    const __nv_bfloat16* Wgh = Whi + (size_t)blockIdx.x * 128 * K;
    const __nv_bfloat16* Wgl = Wlo + (size_t)blockIdx.x * 128 * K;
    const int NC = K >> 5;              // chunks of K=32

    auto fill = [&](int c) {
        uint32_t* st = smu + (c % 3) * STG_U32;
        const __nv_bfloat16* s0 = Agh + c * 32;
        const __nv_bfloat16* s1 = Agl + c * 32;
        const __nv_bfloat16* s2 = Wgh + c * 32;
        const __nv_bfloat16* s3 = Wgl + c * 32;
        #pragma unroll
        for (int i = 0; i < 2; i++) {
            int lin = tid + i * 256;            // 0..511
            int r = lin >> 2, q = lin & 3;      // row, 16B-quarter
            uint32_t doff = SWZ(r, q * 4);
            size_t soff = (size_t)r * K + q * 8;
            uint32_t d0 = s2u(st + doff);
            asm volatile("cp.async.cg.shared.global [%0], [%1], 16;" :: "r"(d0),        "l"(s0 + soff));
            asm volatile("cp.async.cg.shared.global [%0], [%1], 16;" :: "r"(d0 + 8192), "l"(s1 + soff));
            asm volatile("cp.async.cg.shared.global [%0], [%1], 16;" :: "r"(d0 + 16384),"l"(s2 + soff));
            asm volatile("cp.async.cg.shared.global [%0], [%1], 16;" :: "r"(d0 + 24576),"l"(s3 + soff));
        }
    };

    float acc[2][8][4] = {};

    fill(0); asm volatile("cp.async.commit_group;" ::: "memory");
    fill(1); asm volatile("cp.async.commit_group;" ::: "memory");

    for (int c = 0; c < NC; c++) {
        asm volatile("cp.async.wait_group 1;" ::: "memory");
        __syncthreads();
        if (c + 2 < NC) fill(c + 2);
        asm volatile("cp.async.commit_group;" ::: "memory");

        const uint32_t* st  = smu + (c % 3) * STG_U32;
        const uint32_t* sAh = st;
        const uint32_t* sAl = st + 2048;
        const uint32_t* sBh = st + 4096;
        const uint32_t* sBl = st + 6144;

        #pragma unroll
        for (int ks = 0; ks < 2; ks++) {
            const int j0 = ks * 8 + t;
            uint32_t ah[2][4], al[2][4];
            #pragma unroll
            for (int mt = 0; mt < 2; mt++) {
                int r0 = wm + mt * 16 + g, r1 = r0 + 8;
                ah[mt][0] = sAh[SWZ(r0, j0)];     ah[mt][1] = sAh[SWZ(r1, j0)];
                ah[mt][2] = sAh[SWZ(r0, j0 + 4)]; ah[mt][3] = sAh[SWZ(r1, j0 + 4)];
                al[mt][0] = sAl[SWZ(r0, j0)];     al[mt][1] = sAl[SWZ(r1, j0)];
                al[mt][2] = sAl[SWZ(r0, j0 + 4)]; al[mt][3] = sAl[SWZ(r1, j0 + 4)];
            }
            #pragma unroll
            for (int nt = 0; nt < 8; nt++) {
                int r = wn + nt * 8 + g;
                uint32_t bh[2] = { sBh[SWZ(r, j0)], sBh[SWZ(r, j0 + 4)] };
                uint32_t bl[2] = { sBl[SWZ(r, j0)], sBl[SWZ(r, j0 + 4)] };
                #pragma unroll
                for (int mt = 0; mt < 2; mt++) {
                    mma16(acc[mt][nt], ah[mt], bh);
                    mma16(acc[mt][nt], ah[mt], bl);
                    mma16(acc[mt][nt], al[mt], bh);
                }
            }
        }
    }

    // ---- epilogue ----
    const size_t rbase = (size_t)blockIdx.y * 128 + wm;
    const int    cbase = blockIdx.x * 128 + wn;
    #pragma unroll
    for (int mt = 0; mt < 2; mt++) {
        #pragma unroll
        for (int half = 0; half < 2; half++) {
            size_t row = rbase + mt * 16 + half * 8 + g;
            size_t rowoff = row * (size_t)N;
            #pragma unroll
            for (int nt = 0; nt < 8; nt++) {
                int col = cbase + nt * 8 + 2 * t;
                float v0 = acc[mt][nt][half * 2 + 0];
                float v1 = acc[mt][nt][half * 2 + 1];
                if (bias) {
                    v0 += __ldg(bias + col);
                    v1 += __ldg(bias + col + 1);
                }
                if (EPI == 1) {
                    float2 rv = *(const float2*)(res + rowoff + col);
                    v0 += rv.x; v1 += rv.y;
                }
                if (EPI == 2) {
                    v0 = v0 / (1.f + __expf(-v0));
                    v1 = v1 / (1.f + __expf(-v1));
                }
                float2 ov; ov.x = v0; ov.y = v1;
                *(float2*)(C + rowoff + col) = ov;
            }
        }
    }
}

// ---------------- flash attention (fp32, causal) -> hi/lo bf16 planes --------
#define LDSA 68
__global__ void __launch_bounds__(256)
attn_kernel(const float* __restrict__ qkv,
            __nv_bfloat16* __restrict__ oh, __nv_bfloat16* __restrict__ ol)
{
    extern __shared__ float smf[];
    float* Qs = smf;
    float* Ks = Qs + 64 * LDSA;
    float* Vs = Ks + 64 * LDSA;
    float* Ps = Vs + 64 * LDSA;

    const int qb  = blockIdx.x;
    const int bh  = blockIdx.y;
    const int bb  = bh >> 4;
    const int hh  = bh & 15;
    const int tid = threadIdx.x;
    const int tm  = tid >> 4, tn = tid & 15;
    const int r0  = tm * 4, c0 = tn * 4;

    for (int i = tid; i < 64 * 16; i += 256) {
        int r = i >> 4, c4 = (i & 15) << 2;
        size_t gidx = ((size_t)(bb * TT + qb * 64 + r) * 3) * DD + hh * HDD + c4;
        float4 v = *(const float4*)(qkv + gidx);
        float* d = &Qs[r * LDSA + c4];
        d[0] = v.x; d[1] = v.y; d[2] = v.z; d[3] = v.w;
    }

    float accO[4][4] = {};
    float mrow[4] = {-1e30f, -1e30f, -1e30f, -1e30f};
    float lrow[4] = {};

    for (int kb = 0; kb <= qb; kb++) {
        __syncthreads();
        for (int i = tid; i < 64 * 16; i += 256) {
            int r = i >> 4, c4 = (i & 15) << 2;
            size_t base = ((size_t)(bb * TT + kb * 64 + r) * 3) * DD + hh * HDD + c4;
            float4 kv = *(const float4*)(qkv + base + DD);
            float4 vv = *(const float4*)(qkv + base + 2 * DD);
            float* dk = &Ks[r * LDSA + c4];
            float* dv = &Vs[r * LDSA + c4];
            dk[0]=kv.x; dk[1]=kv.y; dk[2]=kv.z; dk[3]=kv.w;
            dv[0]=vv.x; dv[1]=vv.y; dv[2]=vv.z; dv[3]=vv.w;
        }
        __syncthreads();

        float s[4][4] = {};
        #pragma unroll
        for (int d = 0; d < 64; d += 4) {
            float4 qv[4], kv[4];
            #pragma unroll
            for (int i = 0; i < 4; i++) qv[i] = *(const float4*)&Qs[(r0+i)*LDSA + d];
            #pragma unroll
            for (int j = 0; j < 4; j++) kv[j] = *(const float4*)&Ks[(c0+j)*LDSA + d];
            #pragma unroll
            for (int i = 0; i < 4; i++)
                #pragma unroll
                for (int j = 0; j < 4; j++)
                    s[i][j] += qv[i].x*kv[j].x + qv[i].y*kv[j].y
                             + qv[i].z*kv[j].z + qv[i].w*kv[j].w;
        }
        #pragma unroll
        for (int i = 0; i < 4; i++) {
            int qi = qb * 64 + r0 + i;
            #pragma unroll
            for (int j = 0; j < 4; j++) {
                int ki = kb * 64 + c0 + j;
                float v = s[i][j] * 0.125f;
                s[i][j] = (ki > qi) ? -1e30f : v;
            }
        }
        #pragma unroll
        for (int i = 0; i < 4; i++) {
            float rm = fmaxf(fmaxf(s[i][0], s[i][1]), fmaxf(s[i][2], s[i][3]));
            #pragma unroll
            for (int off = 8; off; off >>= 1)
                rm = fmaxf(rm, __shfl_xor_sync(0xffffffffu, rm, off));
            float mnew  = fmaxf(mrow[i], rm);
            float alpha = __expf(mrow[i] - mnew);
            mrow[i] = mnew;
            float rs = 0.f;
            #pragma unroll
            for (int j = 0; j < 4; j++) {
                float p = __expf(s[i][j] - mnew);
                s[i][j] = p;
                rs += p;
            }
            #pragma unroll
            for (int off = 8; off; off >>= 1)
                rs += __shfl_xor_sync(0xffffffffu, rs, off);
            lrow[i] = lrow[i] * alpha + rs;
            #pragma unroll
            for (int j = 0; j < 4; j++) accO[i][j] *= alpha;
        }
        #pragma unroll
        for (int i = 0; i < 4; i++)
            #pragma unroll
            for (int j = 0; j < 4; j++)
                Ps[(r0+i)*LDSA + c0 + j] = s[i][j];
        __syncthreads();

        #pragma unroll
        for (int jj = 0; jj < 64; jj += 4) {
            float4 pv[4], vv[4];
            #pragma unroll
            for (int i = 0; i < 4; i++) pv[i] = *(const float4*)&Ps[(r0+i)*LDSA + jj];
            #pragma unroll
            for (int tt = 0; tt < 4; tt++) vv[tt] = *(const float4*)&Vs[(jj+tt)*LDSA + c0];
            #pragma unroll
            for (int i = 0; i < 4; i++) {
                accO[i][0] += pv[i].x*vv[0].x + pv[i].y*vv[1].x + pv[i].z*vv[2].x + pv[i].w*vv[3].x;
                accO[i][1] += pv[i].x*vv[0].y + pv[i].y*vv[1].y + pv[i].z*vv[2].y + pv[i].w*vv[3].y;
                accO[i][2] += pv[i].x*vv[0].z + pv[i].y*vv[1].z + pv[i].z*vv[2].z + pv[i].w*vv[3].z;
                accO[i][3] += pv[i].x*vv[0].w + pv[i].y*vv[1].w + pv[i].z*vv[2].w + pv[i].w*vv[3].w;
            }
        }
    }

    #pragma unroll
    for (int i = 0; i < 4; i++) {
        float inv = 1.f / lrow[i];
        int qi = qb * 64 + r0 + i;
        size_t base = ((size_t)(bb * TT + qi) * NHH + hh) * HDD + c0;
        __nv_bfloat16 h0,l0, h1,l1, h2,l2, h3,l3;
        bsplit(accO[i][0] * inv, h0, l0);
        bsplit(accO[i][1] * inv, h1, l1);
        bsplit(accO[i][2] * inv, h2, l2);
        bsplit(accO[i][3] * inv, h3, l3);
        __nv_bfloat162* ph = (__nv_bfloat162*)(oh + base);
        __nv_bfloat162* pl = (__nv_bfloat162*)(ol + base);
        ph[0] = __halves2bfloat162(h0, h1);
        ph[1] = __halves2bfloat162(h2, h3);
        pl[0] = __halves2bfloat162(l0, l1);
        pl[1] = __halves2bfloat162(l2, l3);
    }
}

// ---------------- launch ----------------
extern "C" void kernel_launch(void* const* d_in, const int* in_sizes, int n_in,
                              void* d_out, int out_size)
{
    const int*   x      = (const int*)  d_in[0];
    const float* emb_w  = (const float*)d_in[1];
    const float* n1_w   = (const float*)d_in[2];
    const float* n2_w   = (const float*)d_in[3];
    const float* qkv_w  = (const float*)d_in[4];
    const float* qkv_b  = (const float*)d_in[5];
    const float* o_w    = (const float*)d_in[6];
    const float* o_b    = (const float*)d_in[7];
    const float* g_w    = (const float*)d_in[8];
    const float* g_b    = (const float*)d_in[9];
    const float* u_w    = (const float*)d_in[10];
    const float* u_b    = (const float*)d_in[11];
    const float* dn_w   = (const float*)d_in[12];
    const float* dn_b   = (const float*)d_in[13];
    const float* norm_w = (const float*)d_in[14];
    const float* head_w = (const float*)d_in[15];
    float* out = (float*)d_out;

    float *h, *qkv, *fg, *fu;
    __nv_bfloat16 *nh, *nl, *ah, *al, *fgh, *fgl, *wh, *wl;
    cudaGetSymbolAddress((void**)&h,   g_h);
    cudaGetSymbolAddress((void**)&qkv, g_qkv);
    cudaGetSymbolAddress((void**)&fg,  g_fg);
    cudaGetSymbolAddress((void**)&fu,  g_fu);
    cudaGetSymbolAddress((void**)&nh,  g_nh);
    cudaGetSymbolAddress((void**)&nl,  g_nl);
    cudaGetSymbolAddress((void**)&ah,  g_ah);
    cudaGetSymbolAddress((void**)&al,  g_al);
    cudaGetSymbolAddress((void**)&fgh, g_fgh);
    cudaGetSymbolAddress((void**)&fgl, g_fgl);
    cudaGetSymbolAddress((void**)&wh,  g_wh);
    cudaGetSymbolAddress((void**)&wl,  g_wl);

    const int attn_smem = 4 * 64 * LDSA * sizeof(float);
    cudaFuncSetAttribute(attn_kernel, cudaFuncAttributeMaxDynamicSharedMemorySize, attn_smem);
    cudaFuncSetAttribute(gemm_bf3<0>, cudaFuncAttributeMaxDynamicSharedMemorySize, GEMM_SMEM);
    cudaFuncSetAttribute(gemm_bf3<1>, cudaFuncAttributeMaxDynamicSharedMemorySize, GEMM_SMEM);
    cudaFuncSetAttribute(gemm_bf3<2>, cudaFuncAttributeMaxDynamicSharedMemorySize, GEMM_SMEM);

    auto wsplit = [&](const float* w, int elems) {
        int n4 = elems >> 2;
        wsplit_kernel<<<(n4 + 255) / 256, 256>>>(w, wh, wl, n4);
    };

    embed_kernel<<<MM, 256>>>(x, emb_w, h);

    for (int l = 0; l < NLL; l++) {
        // ---- attention block ----
        rmsnorm_kernel<<<MM, 256>>>(h, n1_w + (size_t)l * DD, nh, nl);
        wsplit(qkv_w + (size_t)l * 3 * DD * DD, 3 * DD * DD);
        gemm_bf3<0><<<dim3(3*DD/128, MM/128), 256, GEMM_SMEM>>>(
            nh, nl, wh, wl, qkv_b + (size_t)l * 3 * DD, nullptr, qkv, 3*DD, DD);
        attn_kernel<<<dim3(TT/64, BB*NHH), 256, attn_smem>>>(qkv, ah, al);
        wsplit(o_w + (size_t)l * DD * DD, DD * DD);
        gemm_bf3<1><<<dim3(DD/128, MM/128), 256, GEMM_SMEM>>>(
            ah, al, wh, wl, o_b + (size_t)l * DD, h, h, DD, DD);
        // ---- FFN block ----
        rmsnorm_kernel<<<MM, 256>>>(h, n2_w + (size_t)l * DD, nh, nl);
        wsplit(g_w + (size_t)l * FFD * DD, FFD * DD);
        gemm_bf3<2><<<dim3(FFD/128, MM/128), 256, GEMM_SMEM>>>(
            nh, nl, wh, wl, g_b + (size_t)l * FFD, nullptr, fg, FFD, DD);
        wsplit(u_w + (size_t)l * FFD * DD, FFD * DD);
        gemm_bf3<0><<<dim3(FFD/128, MM/128), 256, GEMM_SMEM>>>(
            nh, nl, wh, wl, u_b + (size_t)l * FFD, nullptr, fu, FFD, DD);
        mul_kernel<<<(MM*FFD/4 + 255)/256, 256>>>(fg, fu, fgh, fgl, MM*FFD/4);
        wsplit(dn_w + (size_t)l * DD * FFD, DD * FFD);
        gemm_bf3<1><<<dim3(DD/128, MM/128), 256, GEMM_SMEM>>>(
            fgh, fgl, wh, wl, dn_b + (size_t)l * DD, h, h, DD, FFD);
    }

    rmsnorm_kernel<<<MM, 256>>>(h, norm_w, nh, nl);
    wsplit(head_w, VV * DD);
    gemm_bf3<0><<<dim3(VV/128, MM/128), 256, GEMM_SMEM>>>(
        nh, nl, wh, wl, nullptr, nullptr, out, VV, DD);
}